// round 11
// baseline (speedup 1.0000x reference)
#include <cuda_runtime.h>
#include <stdint.h>

// GateLayer: x (4096,4096) f32, idx_l/idx_r (16384,) int, alpha (16384,3) f32,
// y (4096,16384) f32.
#define MDIM    4096
#define GMAX    16384
#define ROWS    4          // rows per tile (one 16-B quad per column)

// Static device scratch (no cudaMalloc allowed)
__device__ __align__(16) int    g_il[GMAX];   // pre-swizzled quad byte offsets
__device__ __align__(16) int    g_ir[GMAX];   // pre-swizzled quad byte offsets
__device__ __align__(16) float2 g_cf[GMAX];

// ---------------------------------------------------------------------------
// Prep with fused int64/int32 detection. Every block samples the first 512
// 32-bit words of il/ir: OR of odd words is 0 iff idx is int64 (values < 4096
// -> high halves zero; if int32 those words are random indices).
// Emits PRE-SWIZZLED smem quad byte offsets:  P(c) = (c ^ ((c>>3)&7)) << 4,
// and folded softmax coeffs: y = c_ab*ab + c_s*(a+b),
//   c_ab = w0-w1-2w2, c_s = w1+w2.
// ---------------------------------------------------------------------------
__global__ void prep_kernel(const unsigned int* __restrict__ il_raw,
                            const unsigned int* __restrict__ ir_raw,
                            const float* __restrict__ alpha, int G) {
    int t = threadIdx.x;
    unsigned int acc = 0;
    int i = t * 2 + 1;
    if (i < min(G, 512)) acc = il_raw[i] | ir_raw[i];
    int is64 = !__syncthreads_or(acc != 0u);

    int g = blockIdx.x * blockDim.x + t;
    if (g >= G) return;
    int il, ir;
    if (is64) { il = (int)il_raw[2 * g]; ir = (int)ir_raw[2 * g]; }
    else      { il = (int)il_raw[g];     ir = (int)ir_raw[g];     }
    g_il[g] = (il ^ ((il >> 3) & 7)) << 4;
    g_ir[g] = (ir ^ ((ir >> 3) & 7)) << 4;

    float a0 = alpha[3 * g + 0], a1 = alpha[3 * g + 1], a2 = alpha[3 * g + 2];
    float m  = fmaxf(a0, fmaxf(a1, a2));
    float e0 = expf(a0 - m), e1 = expf(a1 - m), e2 = expf(a2 - m);
    float inv = 1.0f / (e0 + e1 + e2);
    float w0 = e0 * inv, w1 = e1 * inv, w2 = e2 * inv;
    g_cf[g] = make_float2(w0 - w1 - 2.0f * w2, w1 + w2);
}

// ---------------------------------------------------------------------------
// Main kernel, 2 blocks/SM (staging of one block overlaps gather of the
// other). SMEM holds 4 rows of x TRANSPOSED: column c is ONE 16-B quad
// (rows 0-3) at byte P(c) = (c ^ ((c>>3)&7)) << 4 (bijective).
// Staging: each thread loads the same float4-column from 4 rows (4 coalesced
// LDG.128), transposes in registers, stores 4 quads via STS.128 -- per
// phase-of-8 lanes the bank slots {j^k, (j^4)^k} cover all 8 -> conflict-free.
// Gather: one LDS.128 fetches rows 0-3 of one column. Thread = 4 g x 4 rows
// = 16 outputs/iter: 8 LDS.128 + 4 STG.128 + 4 LDG.128.
// ---------------------------------------------------------------------------
__global__ __launch_bounds__(512, 2)
void gate_kernel(const float* __restrict__ x, float* __restrict__ y,
                 int G, int gPerBlock) {
    extern __shared__ float sm[];
    char* smb = (char*)sm;
    const int tid  = threadIdx.x;
    const int warp = tid >> 5, lane = tid & 31;
    const int row0   = blockIdx.x * ROWS;
    const int gstart = blockIdx.y * gPerBlock;

    // ---- Stage: 4 rows, register transpose, vector STS (conflict-free) ----
    {
        const float4* x0 = (const float4*)(x + (size_t)(row0 + 0) * MDIM);
        const float4* x1 = (const float4*)(x + (size_t)(row0 + 1) * MDIM);
        const float4* x2 = (const float4*)(x + (size_t)(row0 + 2) * MDIM);
        const float4* x3 = (const float4*)(x + (size_t)(row0 + 3) * MDIM);
        #pragma unroll
        for (int o = 0; o < 2; o++) {
            int c4 = (warp * 2 + o) * 32 + lane;     // float4-column 0..1023
            float4 v0 = x0[c4];
            float4 v1 = x1[c4];
            float4 v2 = x2[c4];
            float4 v3 = x3[c4];
            int c0 = c4 * 4;
            #pragma unroll
            for (int j = 0; j < 4; j++) {
                int c = c0 + j;
                int P = (c ^ ((c >> 3) & 7)) << 4;
                *(float4*)(smb + P) =
                    make_float4((&v0.x)[j], (&v1.x)[j], (&v2.x)[j], (&v3.x)[j]);
            }
        }
    }
    __syncthreads();

    float* yrow0 = y + (size_t)row0 * G;

    // 4 g per thread; 512 threads cover 2048 g per sweep.
    #pragma unroll 2
    for (int gb = gstart + tid * 4; gb < gstart + gPerBlock; gb += 2048) {
        int4   P   = *(const int4*)&g_il[gb];         // pre-swizzled offsets
        int4   Q   = *(const int4*)&g_ir[gb];
        float4 cfA = *(const float4*)&g_cf[gb];       // (cab0,cs0,cab1,cs1)
        float4 cfB = *(const float4*)&g_cf[gb + 2];   // (cab2,cs2,cab3,cs3)

        float4 v0, v1, v2, v3;   // v{r} = outputs (g0,g1,g2,g3) at row r

        {   // g-pair 0 (g0, g1)
            float4 a0 = *(const float4*)(smb + P.x);
            float4 b0 = *(const float4*)(smb + Q.x);
            float4 a1 = *(const float4*)(smb + P.y);
            float4 b1 = *(const float4*)(smb + Q.y);
            v0.x = fmaf(cfA.x, a0.x * b0.x, cfA.y * (a0.x + b0.x));
            v1.x = fmaf(cfA.x, a0.y * b0.y, cfA.y * (a0.y + b0.y));
            v2.x = fmaf(cfA.x, a0.z * b0.z, cfA.y * (a0.z + b0.z));
            v3.x = fmaf(cfA.x, a0.w * b0.w, cfA.y * (a0.w + b0.w));
            v0.y = fmaf(cfA.z, a1.x * b1.x, cfA.w * (a1.x + b1.x));
            v1.y = fmaf(cfA.z, a1.y * b1.y, cfA.w * (a1.y + b1.y));
            v2.y = fmaf(cfA.z, a1.z * b1.z, cfA.w * (a1.z + b1.z));
            v3.y = fmaf(cfA.z, a1.w * b1.w, cfA.w * (a1.w + b1.w));
        }
        {   // g-pair 1 (g2, g3)
            float4 a2 = *(const float4*)(smb + P.z);
            float4 b2 = *(const float4*)(smb + Q.z);
            float4 a3 = *(const float4*)(smb + P.w);
            float4 b3 = *(const float4*)(smb + Q.w);
            v0.z = fmaf(cfB.x, a2.x * b2.x, cfB.y * (a2.x + b2.x));
            v1.z = fmaf(cfB.x, a2.y * b2.y, cfB.y * (a2.y + b2.y));
            v2.z = fmaf(cfB.x, a2.z * b2.z, cfB.y * (a2.z + b2.z));
            v3.z = fmaf(cfB.x, a2.w * b2.w, cfB.y * (a2.w + b2.w));
            v0.w = fmaf(cfB.z, a3.x * b3.x, cfB.w * (a3.x + b3.x));
            v1.w = fmaf(cfB.z, a3.y * b3.y, cfB.w * (a3.y + b3.y));
            v2.w = fmaf(cfB.z, a3.z * b3.z, cfB.w * (a3.z + b3.z));
            v3.w = fmaf(cfB.z, a3.w * b3.w, cfB.w * (a3.w + b3.w));
        }

        // 4 coalesced STG.128 (warp: 32 lanes x 16 B = one dense 512-B row)
        float* yp = yrow0 + gb;
        *(float4*)(yp + 0 * (size_t)G) = v0;
        *(float4*)(yp + 1 * (size_t)G) = v1;
        *(float4*)(yp + 2 * (size_t)G) = v2;
        *(float4*)(yp + 3 * (size_t)G) = v3;
    }
}

// ---------------------------------------------------------------------------
extern "C" void kernel_launch(void* const* d_in, const int* in_sizes, int n_in,
                              void* d_out, int out_size) {
    const float*        x     = (const float*)d_in[0];
    const unsigned int* il    = (const unsigned int*)d_in[1];
    const unsigned int* ir    = (const unsigned int*)d_in[2];
    const float*        alpha = (const float*)d_in[3];
    float*              y     = (float*)d_out;

    const int G = in_sizes[1];               // 16384
    const int B = in_sizes[0] / MDIM;        // 4096

    prep_kernel<<<(G + 255) / 256, 256>>>(il, ir, alpha, G);

    const int smemBytes = MDIM * 16;         // 65536 B (one quad per column)
    cudaFuncSetAttribute(gate_kernel, cudaFuncAttributeMaxDynamicSharedMemorySize,
                         smemBytes);

    dim3 grid(B / ROWS, 2);                  // (1024, 2), gPerBlock = G/2
    gate_kernel<<<grid, 512, smemBytes>>>(x, y, G, G / 2);
}

// round 12
// speedup vs baseline: 1.4371x; 1.4371x over previous
#include <cuda_runtime.h>
#include <stdint.h>

// GateLayer: x (4096,4096) f32, idx_l/idx_r (16384,) int, alpha (16384,3) f32,
// y (4096,16384) f32.
#define MDIM    4096
#define GMAX    16384
#define ROWS    4          // rows per tile (one 16-B quad per column)

// Static device scratch (no cudaMalloc allowed)
__device__ __align__(16) int    g_il[GMAX];
__device__ __align__(16) int    g_ir[GMAX];
__device__ __align__(16) float2 g_cf[GMAX];

// ---------------------------------------------------------------------------
// Prep with fused int64/int32 detection. Every block samples the first 512
// 32-bit words of il/ir: OR of odd words is 0 iff idx is int64 (values < 4096
// -> high halves zero; if int32 those words are random indices, so the OR is
// nonzero w.o.p.). All blocks reach the same decision independently.
// Emits RAW column indices and folded softmax coeffs:
//   y = c_ab*ab + c_s*(a+b),  c_ab = w0-w1-2w2, c_s = w1+w2.
// ---------------------------------------------------------------------------
__global__ void prep_kernel(const unsigned int* __restrict__ il_raw,
                            const unsigned int* __restrict__ ir_raw,
                            const float* __restrict__ alpha, int G) {
    int t = threadIdx.x;
    unsigned int acc = 0;
    int i = t * 2 + 1;
    if (i < min(G, 512)) acc = il_raw[i] | ir_raw[i];
    int is64 = !__syncthreads_or(acc != 0u);

    int g = blockIdx.x * blockDim.x + t;
    if (g >= G) return;
    int il, ir;
    if (is64) { il = (int)il_raw[2 * g]; ir = (int)ir_raw[2 * g]; }
    else      { il = (int)il_raw[g];     ir = (int)ir_raw[g];     }
    g_il[g] = il;
    g_ir[g] = ir;

    float a0 = alpha[3 * g + 0], a1 = alpha[3 * g + 1], a2 = alpha[3 * g + 2];
    float m  = fmaxf(a0, fmaxf(a1, a2));
    float e0 = expf(a0 - m), e1 = expf(a1 - m), e2 = expf(a2 - m);
    float inv = 1.0f / (e0 + e1 + e2);
    float w0 = e0 * inv, w1 = e1 * inv, w2 = e2 * inv;
    g_cf[g] = make_float2(w0 - w1 - 2.0f * w2, w1 + w2);
}

// ---------------------------------------------------------------------------
// Main kernel, 2 blocks/SM (staging of one block overlaps gather of the
// other). SMEM holds 4 rows of x TRANSPOSED: column c is ONE 16-B quad (rows
// 0-3) at byte P(c) = (c ^ ((c>>3)&7)) << 4   (bijective; staging STS
// conflict-free: for each float4 component j, the 8 lanes of a phase cover
// all 8 bank slots). One LDS.128 gathers rows 0-3 of one column.
// Thread = 4 g x 4 rows = 16 outputs/iter:
//   8 LDS.128 + 4 STG.128 + 4 LDG.128 = 16 LSU instructions.
// ---------------------------------------------------------------------------
__global__ __launch_bounds__(512, 2)
void gate_kernel(const float* __restrict__ x, float* __restrict__ y,
                 int G, int gPerBlock) {
    extern __shared__ float sm[];
    char* smb = (char*)sm;
    const int tid  = threadIdx.x;
    const int warp = tid >> 5, lane = tid & 31;
    const int row0   = blockIdx.x * ROWS;
    const int gstart = blockIdx.y * gPerBlock;

    // ---- Stage: 4 rows, transposed + swizzled, conflict-free STS ----
    {
        const int r  = lane >> 3;              // 0..3
        const int cs = lane & 7;               // 0..7
        const float4* x4 = (const float4*)(x + (size_t)(row0 + r) * MDIM);
        #pragma unroll
        for (int i = 0; i < 8; i++) {
            int c4 = warp * 8 + cs + i * 128;  // float4 index 0..1023
            float4 v = x4[c4];
            int c0 = c4 * 4;
            #pragma unroll
            for (int j = 0; j < 4; j++) {
                int c = c0 + j;
                int P = ((c ^ ((c >> 3) & 7)) << 4) + r * 4;
                *(float*)(smb + P) = (&v.x)[j];
            }
        }
    }
    __syncthreads();

    float* yrow0 = y + (size_t)row0 * G;

    // 4 g per thread; 512 threads cover 2048 g per sweep.
    #pragma unroll 2
    for (int gb = gstart + tid * 4; gb < gstart + gPerBlock; gb += 2048) {
        int4   il  = *(const int4*)&g_il[gb];
        int4   ir  = *(const int4*)&g_ir[gb];
        float4 cfA = *(const float4*)&g_cf[gb];       // (cab0,cs0,cab1,cs1)
        float4 cfB = *(const float4*)&g_cf[gb + 2];   // (cab2,cs2,cab3,cs3)

        int P0 = (il.x ^ ((il.x >> 3) & 7)) << 4;
        int Q0 = (ir.x ^ ((ir.x >> 3) & 7)) << 4;
        int P1 = (il.y ^ ((il.y >> 3) & 7)) << 4;
        int Q1 = (ir.y ^ ((ir.y >> 3) & 7)) << 4;
        int P2 = (il.z ^ ((il.z >> 3) & 7)) << 4;
        int Q2 = (ir.z ^ ((ir.z >> 3) & 7)) << 4;
        int P3 = (il.w ^ ((il.w >> 3) & 7)) << 4;
        int Q3 = (ir.w ^ ((ir.w >> 3) & 7)) << 4;

        float4 v0, v1, v2, v3;   // v{r} = outputs (g0,g1,g2,g3) at row r

        {   // g-pair 0 (g0, g1)
            float4 a0 = *(const float4*)(smb + P0);
            float4 b0 = *(const float4*)(smb + Q0);
            float4 a1 = *(const float4*)(smb + P1);
            float4 b1 = *(const float4*)(smb + Q1);
            v0.x = fmaf(cfA.x, a0.x * b0.x, cfA.y * (a0.x + b0.x));
            v1.x = fmaf(cfA.x, a0.y * b0.y, cfA.y * (a0.y + b0.y));
            v2.x = fmaf(cfA.x, a0.z * b0.z, cfA.y * (a0.z + b0.z));
            v3.x = fmaf(cfA.x, a0.w * b0.w, cfA.y * (a0.w + b0.w));
            v0.y = fmaf(cfA.z, a1.x * b1.x, cfA.w * (a1.x + b1.x));
            v1.y = fmaf(cfA.z, a1.y * b1.y, cfA.w * (a1.y + b1.y));
            v2.y = fmaf(cfA.z, a1.z * b1.z, cfA.w * (a1.z + b1.z));
            v3.y = fmaf(cfA.z, a1.w * b1.w, cfA.w * (a1.w + b1.w));
        }
        {   // g-pair 1 (g2, g3)
            float4 a2 = *(const float4*)(smb + P2);
            float4 b2 = *(const float4*)(smb + Q2);
            float4 a3 = *(const float4*)(smb + P3);
            float4 b3 = *(const float4*)(smb + Q3);
            v0.z = fmaf(cfB.x, a2.x * b2.x, cfB.y * (a2.x + b2.x));
            v1.z = fmaf(cfB.x, a2.y * b2.y, cfB.y * (a2.y + b2.y));
            v2.z = fmaf(cfB.x, a2.z * b2.z, cfB.y * (a2.z + b2.z));
            v3.z = fmaf(cfB.x, a2.w * b2.w, cfB.y * (a2.w + b2.w));
            v0.w = fmaf(cfB.z, a3.x * b3.x, cfB.w * (a3.x + b3.x));
            v1.w = fmaf(cfB.z, a3.y * b3.y, cfB.w * (a3.y + b3.y));
            v2.w = fmaf(cfB.z, a3.z * b3.z, cfB.w * (a3.z + b3.z));
            v3.w = fmaf(cfB.z, a3.w * b3.w, cfB.w * (a3.w + b3.w));
        }

        // 4 coalesced STG.128 (warp: 32 lanes x 16 B = one dense 512-B row)
        float* yp = yrow0 + gb;
        *(float4*)(yp + 0 * (size_t)G) = v0;
        *(float4*)(yp + 1 * (size_t)G) = v1;
        *(float4*)(yp + 2 * (size_t)G) = v2;
        *(float4*)(yp + 3 * (size_t)G) = v3;
    }
}

// ---------------------------------------------------------------------------
extern "C" void kernel_launch(void* const* d_in, const int* in_sizes, int n_in,
                              void* d_out, int out_size) {
    const float*        x     = (const float*)d_in[0];
    const unsigned int* il    = (const unsigned int*)d_in[1];
    const unsigned int* ir    = (const unsigned int*)d_in[2];
    const float*        alpha = (const float*)d_in[3];
    float*              y     = (float*)d_out;

    const int G = in_sizes[1];               // 16384
    const int B = in_sizes[0] / MDIM;        // 4096

    prep_kernel<<<(G + 255) / 256, 256>>>(il, ir, alpha, G);

    const int smemBytes = MDIM * 16;         // 65536 B (one quad per column)
    cudaFuncSetAttribute(gate_kernel, cudaFuncAttributeMaxDynamicSharedMemorySize,
                         smemBytes);

    dim3 grid(B / ROWS, 2);                  // (1024, 2), gPerBlock = G/2
    gate_kernel<<<grid, 512, smemBytes>>>(x, y, G, G / 2);
}

// round 13
// speedup vs baseline: 1.6027x; 1.1152x over previous
#include <cuda_runtime.h>
#include <stdint.h>

// GateLayer: x (4096,4096) f32, idx_l/idx_r (16384,) int, alpha (16384,3) f32,
// y (4096,16384) f32.
#define MDIM    4096
#define GMAX    16384
#define ROWS    4          // rows per tile (one 16-B quad per column)

// Static device scratch (no cudaMalloc allowed)
__device__ __align__(16) int    g_il[GMAX];
__device__ __align__(16) int    g_ir[GMAX];
__device__ __align__(16) float2 g_cf[GMAX];

// ---------------------------------------------------------------------------
// Prep with fused int64/int32 detection. Every block samples the first 512
// 32-bit words of il/ir: OR of odd words is 0 iff idx is int64 (values < 4096
// -> high halves zero; if int32 those words are random indices, so the OR is
// nonzero w.o.p.). All blocks reach the same decision independently.
// Emits RAW column indices and folded softmax coeffs:
//   y = c_ab*ab + c_s*(a+b),  c_ab = w0-w1-2w2, c_s = w1+w2.
// ---------------------------------------------------------------------------
__global__ void prep_kernel(const unsigned int* __restrict__ il_raw,
                            const unsigned int* __restrict__ ir_raw,
                            const float* __restrict__ alpha, int G) {
    int t = threadIdx.x;
    unsigned int acc = 0;
    int i = t * 2 + 1;
    if (i < min(G, 512)) acc = il_raw[i] | ir_raw[i];
    int is64 = !__syncthreads_or(acc != 0u);

    int g = blockIdx.x * blockDim.x + t;
    if (g >= G) return;
    int il, ir;
    if (is64) { il = (int)il_raw[2 * g]; ir = (int)ir_raw[2 * g]; }
    else      { il = (int)il_raw[g];     ir = (int)ir_raw[g];     }
    g_il[g] = il;
    g_ir[g] = ir;

    float a0 = alpha[3 * g + 0], a1 = alpha[3 * g + 1], a2 = alpha[3 * g + 2];
    float m  = fmaxf(a0, fmaxf(a1, a2));
    float e0 = expf(a0 - m), e1 = expf(a1 - m), e2 = expf(a2 - m);
    float inv = 1.0f / (e0 + e1 + e2);
    float w0 = e0 * inv, w1 = e1 * inv, w2 = e2 * inv;
    g_cf[g] = make_float2(w0 - w1 - 2.0f * w2, w1 + w2);
}

// ---------------------------------------------------------------------------
// Main kernel, 2 blocks/SM (staging of one block overlaps gather of the
// other). Each block stages its 4-row x tile ONCE and sweeps ALL of g
// (grid.y merge: halves staging DRAM reads + staging crossbar/LSU work).
// SMEM holds 4 rows of x TRANSPOSED: column c is ONE 16-B quad (rows 0-3) at
// byte P(c) = (c ^ ((c>>3)&7)) << 4   (bijective; staging STS conflict-free:
// for each float4 component j, the 8 lanes of a phase cover all 8 bank
// slots). One LDS.128 gathers rows 0-3 of one column.
// Thread = 4 g x 4 rows = 16 outputs/iter:
//   8 LDS.128 + 4 STG.128 + 4 LDG.128 = 16 LSU instructions.
// ---------------------------------------------------------------------------
__global__ __launch_bounds__(512, 2)
void gate_kernel(const float* __restrict__ x, float* __restrict__ y,
                 int G, int gPerBlock) {
    extern __shared__ float sm[];
    char* smb = (char*)sm;
    const int tid  = threadIdx.x;
    const int warp = tid >> 5, lane = tid & 31;
    const int row0   = blockIdx.x * ROWS;
    const int gstart = blockIdx.y * gPerBlock;

    // ---- Stage: 4 rows, transposed + swizzled, conflict-free STS ----
    {
        const int r  = lane >> 3;              // 0..3
        const int cs = lane & 7;               // 0..7
        const float4* x4 = (const float4*)(x + (size_t)(row0 + r) * MDIM);
        #pragma unroll
        for (int i = 0; i < 8; i++) {
            int c4 = warp * 8 + cs + i * 128;  // float4 index 0..1023
            float4 v = x4[c4];
            int c0 = c4 * 4;
            #pragma unroll
            for (int j = 0; j < 4; j++) {
                int c = c0 + j;
                int P = ((c ^ ((c >> 3) & 7)) << 4) + r * 4;
                *(float*)(smb + P) = (&v.x)[j];
            }
        }
    }
    __syncthreads();

    float* yrow0 = y + (size_t)row0 * G;

    // 4 g per thread; 512 threads cover 2048 g per sweep; 8 sweeps cover G.
    #pragma unroll 1
    for (int gb = gstart + tid * 4; gb < gstart + gPerBlock; gb += 2048) {
        int4   il  = *(const int4*)&g_il[gb];
        int4   ir  = *(const int4*)&g_ir[gb];
        float4 cfA = *(const float4*)&g_cf[gb];       // (cab0,cs0,cab1,cs1)
        float4 cfB = *(const float4*)&g_cf[gb + 2];   // (cab2,cs2,cab3,cs3)

        int P0 = (il.x ^ ((il.x >> 3) & 7)) << 4;
        int Q0 = (ir.x ^ ((ir.x >> 3) & 7)) << 4;
        int P1 = (il.y ^ ((il.y >> 3) & 7)) << 4;
        int Q1 = (ir.y ^ ((ir.y >> 3) & 7)) << 4;
        int P2 = (il.z ^ ((il.z >> 3) & 7)) << 4;
        int Q2 = (ir.z ^ ((ir.z >> 3) & 7)) << 4;
        int P3 = (il.w ^ ((il.w >> 3) & 7)) << 4;
        int Q3 = (ir.w ^ ((ir.w >> 3) & 7)) << 4;

        float4 v0, v1, v2, v3;   // v{r} = outputs (g0,g1,g2,g3) at row r

        {   // g-pair 0 (g0, g1)
            float4 a0 = *(const float4*)(smb + P0);
            float4 b0 = *(const float4*)(smb + Q0);
            float4 a1 = *(const float4*)(smb + P1);
            float4 b1 = *(const float4*)(smb + Q1);
            v0.x = fmaf(cfA.x, a0.x * b0.x, cfA.y * (a0.x + b0.x));
            v1.x = fmaf(cfA.x, a0.y * b0.y, cfA.y * (a0.y + b0.y));
            v2.x = fmaf(cfA.x, a0.z * b0.z, cfA.y * (a0.z + b0.z));
            v3.x = fmaf(cfA.x, a0.w * b0.w, cfA.y * (a0.w + b0.w));
            v0.y = fmaf(cfA.z, a1.x * b1.x, cfA.w * (a1.x + b1.x));
            v1.y = fmaf(cfA.z, a1.y * b1.y, cfA.w * (a1.y + b1.y));
            v2.y = fmaf(cfA.z, a1.z * b1.z, cfA.w * (a1.z + b1.z));
            v3.y = fmaf(cfA.z, a1.w * b1.w, cfA.w * (a1.w + b1.w));
        }
        {   // g-pair 1 (g2, g3)
            float4 a2 = *(const float4*)(smb + P2);
            float4 b2 = *(const float4*)(smb + Q2);
            float4 a3 = *(const float4*)(smb + P3);
            float4 b3 = *(const float4*)(smb + Q3);
            v0.z = fmaf(cfB.x, a2.x * b2.x, cfB.y * (a2.x + b2.x));
            v1.z = fmaf(cfB.x, a2.y * b2.y, cfB.y * (a2.y + b2.y));
            v2.z = fmaf(cfB.x, a2.z * b2.z, cfB.y * (a2.z + b2.z));
            v3.z = fmaf(cfB.x, a2.w * b2.w, cfB.y * (a2.w + b2.w));
            v0.w = fmaf(cfB.z, a3.x * b3.x, cfB.w * (a3.x + b3.x));
            v1.w = fmaf(cfB.z, a3.y * b3.y, cfB.w * (a3.y + b3.y));
            v2.w = fmaf(cfB.z, a3.z * b3.z, cfB.w * (a3.z + b3.z));
            v3.w = fmaf(cfB.z, a3.w * b3.w, cfB.w * (a3.w + b3.w));
        }

        // 4 coalesced STG.128 (warp: 32 lanes x 16 B = one dense 512-B row)
        float* yp = yrow0 + gb;
        *(float4*)(yp + 0 * (size_t)G) = v0;
        *(float4*)(yp + 1 * (size_t)G) = v1;
        *(float4*)(yp + 2 * (size_t)G) = v2;
        *(float4*)(yp + 3 * (size_t)G) = v3;
    }
}

// ---------------------------------------------------------------------------
extern "C" void kernel_launch(void* const* d_in, const int* in_sizes, int n_in,
                              void* d_out, int out_size) {
    const float*        x     = (const float*)d_in[0];
    const unsigned int* il    = (const unsigned int*)d_in[1];
    const unsigned int* ir    = (const unsigned int*)d_in[2];
    const float*        alpha = (const float*)d_in[3];
    float*              y     = (float*)d_out;

    const int G = in_sizes[1];               // 16384
    const int B = in_sizes[0] / MDIM;        // 4096

    prep_kernel<<<(G + 255) / 256, 256>>>(il, ir, alpha, G);

    const int smemBytes = MDIM * 16;         // 65536 B (one quad per column)
    cudaFuncSetAttribute(gate_kernel, cudaFuncAttributeMaxDynamicSharedMemorySize,
                         smemBytes);

    dim3 grid(B / ROWS, 1);                  // 1024 blocks; each sweeps all G
    gate_kernel<<<grid, 512, smemBytes>>>(x, y, G, G);
}